// round 9
// baseline (speedup 1.0000x reference)
#include <cuda_runtime.h>
#include <cuda_bf16.h>
#include <cstdint>

#define NU 200000
#define NI 200000
#define D  64
#define MAXE 2000000
#define NB_I ((NI + 255) / 256)
#define NB_U ((NU + 255) / 256)
#define NSM 148

// ---------------------------------------------------------------------------
// Device scratch (no cudaMalloc allowed)
// ---------------------------------------------------------------------------
__device__ float g_acc_i[(size_t)NI * D];
__device__ float g_acc_u[(size_t)NU * D];
__device__ float g_h_i[(size_t)NI * D];
__device__ float g_h_u[(size_t)NU * D];
__device__ int g_deg_i[NI];
__device__ int g_deg_u[NU];
__device__ int g_rp_i[NI + 1];
__device__ int g_rp_u[NU + 1];
__device__ int g_cur_i[NI];
__device__ int g_cur_u[NU];
__device__ int g_perm_ui[MAXE];
__device__ int g_perm_iu[MAXE];
__device__ int g_bsum_i[1024];
__device__ int g_boff_i[1024];
__device__ int g_bsum_u[1024];
__device__ int g_boff_u[1024];
__device__ __nv_bfloat16 g_Bhi[4][64 * 128];
__device__ __nv_bfloat16 g_Blo[4][64 * 128];

__device__ __forceinline__ uint32_t smem_to_u32(const void* p) {
    uint32_t a;
    asm("{ .reg .u64 t; cvta.to.shared.u64 t, %1; cvt.u32.u64 %0, t; }"
        : "=r"(a) : "l"(p));
    return a;
}

// ---------------------------------------------------------------------------
// Weight prepack
// ---------------------------------------------------------------------------
__global__ void prepack_w_k(const float* __restrict__ W1l_ui, const float* __restrict__ W1r_ui,
                            const float* __restrict__ W1l_iu, const float* __restrict__ W1r_iu,
                            const float* __restrict__ W2l_ui, const float* __restrict__ W2r_ui,
                            const float* __restrict__ W2l_iu, const float* __restrict__ W2r_iu)
{
    int i = blockIdx.x * blockDim.x + threadIdx.x;
    if (i >= 4 * 64 * 128) return;
    int set = i >> 13;
    int n = (i >> 7) & 63;
    int k = i & 127;
    const float* Wl; const float* Wr;
    switch (set) {
        case 0: Wl = W1l_ui; Wr = W1r_ui; break;
        case 1: Wl = W1l_iu; Wr = W1r_iu; break;
        case 2: Wl = W2l_ui; Wr = W2r_ui; break;
        default: Wl = W2l_iu; Wr = W2r_iu; break;
    }
    float w = (k < 64) ? Wl[k * D + n] : Wr[(k - 64) * D + n];
    __nv_bfloat16 hi = __float2bfloat16(w);
    __nv_bfloat16 lo = __float2bfloat16(w - __bfloat162float(hi));
    g_Bhi[set][n * 128 + k] = hi;
    g_Blo[set][n * 128 + k] = lo;
}

// ---------------------------------------------------------------------------
// CSR build — both sides per launch
// ---------------------------------------------------------------------------
__global__ void hist2_k(const int* __restrict__ dst0, int E0, int* __restrict__ deg0,
                        const int* __restrict__ dst1, int E1, int* __restrict__ deg1)
{
    int i = blockIdx.x * blockDim.x + threadIdx.x;
    if (i < E0) atomicAdd(&deg0[__ldg(dst0 + i)], 1);
    else if (i < E0 + E1) atomicAdd(&deg1[__ldg(dst1 + (i - E0))], 1);
}

__global__ void scanA2_k(const int* __restrict__ deg0, int N0, int* __restrict__ bsum0,
                         const int* __restrict__ deg1, int N1, int* __restrict__ bsum1,
                         int nb0)
{
    __shared__ int s[256];
    int tid = threadIdx.x;
    int side = blockIdx.x >= nb0;
    int blk = side ? blockIdx.x - nb0 : blockIdx.x;
    const int* deg = side ? deg1 : deg0;
    int N = side ? N1 : N0;
    int* bsum = side ? bsum1 : bsum0;
    int i = blk * 256 + tid;
    s[tid] = (i < N) ? deg[i] : 0;
    __syncthreads();
    #pragma unroll
    for (int o = 128; o; o >>= 1) {
        if (tid < o) s[tid] += s[tid + o];
        __syncthreads();
    }
    if (tid == 0) bsum[blk] = s[0];
}

__global__ void scanB2_k(const int* __restrict__ bsum0, int NB0, int* __restrict__ boff0,
                         int* __restrict__ rp0, int N0,
                         const int* __restrict__ bsum1, int NB1, int* __restrict__ boff1,
                         int* __restrict__ rp1, int N1)
{
    __shared__ int s[1024];
    int tid = threadIdx.x;
    const int* bsum = blockIdx.x ? bsum1 : bsum0;
    int NB = blockIdx.x ? NB1 : NB0;
    int* boff = blockIdx.x ? boff1 : boff0;
    int* rowptr = blockIdx.x ? rp1 : rp0;
    int N = blockIdx.x ? N1 : N0;
    int v = (tid < NB) ? bsum[tid] : 0;
    s[tid] = v;
    __syncthreads();
    for (int o = 1; o < 1024; o <<= 1) {
        int t = (tid >= o) ? s[tid - o] : 0;
        __syncthreads();
        s[tid] += t;
        __syncthreads();
    }
    if (tid < NB) boff[tid] = s[tid] - v;
    if (tid == NB - 1) rowptr[N] = s[tid];
}

__global__ void scanC2_k(const int* __restrict__ deg0, int N0, const int* __restrict__ boff0,
                         int* __restrict__ rp0, int* __restrict__ cur0,
                         const int* __restrict__ deg1, int N1, const int* __restrict__ boff1,
                         int* __restrict__ rp1, int* __restrict__ cur1,
                         int nb0)
{
    __shared__ int s[256];
    int tid = threadIdx.x;
    int side = blockIdx.x >= nb0;
    int blk = side ? blockIdx.x - nb0 : blockIdx.x;
    const int* deg = side ? deg1 : deg0;
    const int* boff = side ? boff1 : boff0;
    int N = side ? N1 : N0;
    int* rowptr = side ? rp1 : rp0;
    int* cursor = side ? cur1 : cur0;
    int i = blk * 256 + tid;
    int v = (i < N) ? deg[i] : 0;
    s[tid] = v;
    __syncthreads();
    #pragma unroll
    for (int o = 1; o < 256; o <<= 1) {
        int t = (tid >= o) ? s[tid - o] : 0;
        __syncthreads();
        s[tid] += t;
        __syncthreads();
    }
    if (i < N) {
        int ex = boff[blk] + s[tid] - v;
        rowptr[i] = ex;
        cursor[i] = ex;
    }
}

__global__ void permute2_k(const int* __restrict__ e0, int E0,
                           int* __restrict__ cur0, int* __restrict__ perm0,
                           const int* __restrict__ e1, int E1,
                           int* __restrict__ cur1, int* __restrict__ perm1)
{
    int i = blockIdx.x * blockDim.x + threadIdx.x;
    if (i < E0) {
        int s = __ldg(e0 + i);
        int d = __ldg(e0 + E0 + i);
        perm0[atomicAdd(&cur0[d], 1)] = s;
    } else if (i < E0 + E1) {
        int j = i - E0;
        int s = __ldg(e1 + j);
        int d = __ldg(e1 + E1 + j);
        perm1[atomicAdd(&cur1[d], 1)] = s;
    }
}

// ---------------------------------------------------------------------------
// Gather-side aggregation (mean), both sides in one launch. Warp per row.
// ---------------------------------------------------------------------------
__global__ void __launch_bounds__(256)
agg2_k(const float* __restrict__ src0, const int* __restrict__ remap0,
       const int* __restrict__ rp0, const int* __restrict__ perm0,
       float* __restrict__ out0, int N0,
       const float* __restrict__ src1, const int* __restrict__ remap1,
       const int* __restrict__ rp1, const int* __restrict__ perm1,
       float* __restrict__ out1, int N1)
{
    int w = (blockIdx.x * blockDim.x + threadIdx.x) >> 5;
    int lane = threadIdx.x & 31;
    if (w >= N0 + N1) return;

    const float* src; const int* remap; const int* rowptr; const int* perm;
    float* outm;
    if (w < N0) {
        src = src0; remap = remap0; rowptr = rp0; perm = perm0; outm = out0;
    } else {
        w -= N0;
        src = src1; remap = remap1; rowptr = rp1; perm = perm1; outm = out1;
    }

    int start = __ldg(rowptr + w);
    int end   = __ldg(rowptr + w + 1);

    float ax = 0.0f, ay = 0.0f;
    for (int base = start; base < end; base += 32) {
        int rem = end - base;
        int idx = 0;
        if (lane < rem) {
            idx = __ldg(perm + base + lane);
            if (remap) idx = __ldg(remap + idx);
        }
        int m = rem < 32 ? rem : 32;
        for (int j = 0; j < m; j++) {
            int s2 = __shfl_sync(0xffffffffu, idx, j);
            float2 v = *reinterpret_cast<const float2*>(src + (size_t)s2 * D + lane * 2);
            ax += v.x;
            ay += v.y;
        }
    }

    int deg = end - start;
    float inv = (deg > 0) ? (1.0f / (float)deg) : 0.0f;
    float2 o;
    o.x = ax * inv;
    o.y = ay * inv;
    *reinterpret_cast<float2*>(outm + (size_t)w * D + lane * 2) = o;
}

// ---------------------------------------------------------------------------
// Persistent post GEMM (mma.sync m16n8k16 bf16, 3-pass fp32 emulation).
// Grid = 2*NSM blocks: blocks [0,NSM) -> side 0, [NSM,2*NSM) -> side 1.
// Each block stages its side's B+bias ONCE, then loops over row tiles.
// ---------------------------------------------------------------------------
#define PKB 272
#define SM_AHI  0
#define SM_ALO  (128 * PKB)
#define SM_BHI  (2 * 128 * PKB)
#define SM_BLO  (SM_BHI + 64 * PKB)
#define SM_BIAS (SM_BHI + 2 * 64 * PKB)
#define POST_SMEM (SM_BIAS + 256)

#define LDMATRIX_X4(r0, r1, r2, r3, addr) \
    asm volatile("ldmatrix.sync.aligned.m8n8.x4.shared.b16 {%0, %1, %2, %3}, [%4];" \
                 : "=r"(r0), "=r"(r1), "=r"(r2), "=r"(r3) : "r"(addr))

#define MMA_BF16(d, a0, a1, a2, a3, b0, b1) \
    asm volatile("mma.sync.aligned.m16n8k16.row.col.f32.bf16.bf16.f32 " \
                 "{%0, %1, %2, %3}, {%4, %5, %6, %7}, {%8, %9}, {%0, %1, %2, %3};" \
                 : "+f"((d)[0]), "+f"((d)[1]), "+f"((d)[2]), "+f"((d)[3]) \
                 : "r"(a0), "r"(a1), "r"(a2), "r"(a3), "r"(b0), "r"(b1))

__device__ __forceinline__ uint32_t bf2u(__nv_bfloat162 v) {
    return *reinterpret_cast<uint32_t*>(&v);
}

__global__ void __launch_bounds__(256)
sage_post_pers(const float* __restrict__ acc0, const float* __restrict__ x0,
               const int* __restrict__ remap0,
               const __nv_bfloat16* __restrict__ Bhi0, const __nv_bfloat16* __restrict__ Blo0,
               const float* __restrict__ bl0, float* __restrict__ out0, int N0,
               const float* __restrict__ acc1, const float* __restrict__ x1,
               const int* __restrict__ remap1,
               const __nv_bfloat16* __restrict__ Bhi1, const __nv_bfloat16* __restrict__ Blo1,
               const float* __restrict__ bl1, float* __restrict__ out1, int N1,
               int relu)
{
    extern __shared__ char smem[];
    uint32_t sb = smem_to_u32(smem);
    const int tid = threadIdx.x;
    const int warp = tid >> 5;
    const int lane = tid & 31;

    const int side = blockIdx.x >= NSM;
    const int rank = side ? blockIdx.x - NSM : blockIdx.x;
    const float* acc = side ? acc1 : acc0;
    const float* xdst_base = side ? x1 : x0;
    const int* remap = side ? remap1 : remap0;
    const __nv_bfloat16* Bhi = side ? Bhi1 : Bhi0;
    const __nv_bfloat16* Blo = side ? Blo1 : Blo0;
    const float* bl = side ? bl1 : bl0;
    float* out = side ? out1 : out0;
    const int N = side ? N1 : N0;

    // ---- Stage B + bias once ----
    #pragma unroll
    for (int pp = 0; pp < 4; pp++) {
        int i = tid + pp * 256;
        int n = i >> 4;
        int kq = i & 15;
        *reinterpret_cast<uint4*>(smem + SM_BHI + n * PKB + kq * 16) =
            *reinterpret_cast<const uint4*>(Bhi + n * 128 + kq * 8);
        *reinterpret_cast<uint4*>(smem + SM_BLO + n * PKB + kq * 16) =
            *reinterpret_cast<const uint4*>(Blo + n * 128 + kq * 8);
    }
    if (tid < 64) *reinterpret_cast<float*>(smem + SM_BIAS + tid * 4) = bl[tid];

    const uint32_t aRowOff = (uint32_t)(warp * 16 + (lane & 15)) * PKB
                           + (uint32_t)(lane >> 4) * 16;
    const uint32_t bRowOff = (uint32_t)(lane >> 2) * PKB + (uint32_t)(lane & 3) * 4;
    const float* bias = reinterpret_cast<const float*>(smem + SM_BIAS);
    const int cBase = (lane & 3) * 2;
    const int tiles = (N + 127) / 128;

    for (int t = rank; t < tiles; t += NSM) {
        const int r0 = t * 128;

        // ---- Stage A ----
        {
            int row  = tid & 127;
            int half = tid >> 7;
            int gr   = r0 + row;
            bool ok  = (gr < N);
            const float* p;
            if (half == 0) {
                p = acc + (size_t)(ok ? gr : 0) * D;
            } else {
                int xr = ok ? (remap ? __ldg(remap + gr) : gr) : 0;
                p = xdst_base + (size_t)xr * D;
            }
            char* aHiRow = smem + SM_AHI + row * PKB + half * 128;
            char* aLoRow = smem + SM_ALO + row * PKB + half * 128;
            #pragma unroll
            for (int j = 0; j < 8; j++) {
                float4 v0 = ok ? reinterpret_cast<const float4*>(p)[j * 2]
                               : make_float4(0.f, 0.f, 0.f, 0.f);
                float4 v1 = ok ? reinterpret_cast<const float4*>(p)[j * 2 + 1]
                               : make_float4(0.f, 0.f, 0.f, 0.f);
                __nv_bfloat162 h0 = __float22bfloat162_rn(make_float2(v0.x, v0.y));
                __nv_bfloat162 h1 = __float22bfloat162_rn(make_float2(v0.z, v0.w));
                __nv_bfloat162 h2 = __float22bfloat162_rn(make_float2(v1.x, v1.y));
                __nv_bfloat162 h3 = __float22bfloat162_rn(make_float2(v1.z, v1.w));
                float2 f0 = __bfloat1622float2(h0);
                float2 f1 = __bfloat1622float2(h1);
                float2 f2 = __bfloat1622float2(h2);
                float2 f3 = __bfloat1622float2(h3);
                __nv_bfloat162 l0 = __float22bfloat162_rn(make_float2(v0.x - f0.x, v0.y - f0.y));
                __nv_bfloat162 l1 = __float22bfloat162_rn(make_float2(v0.z - f1.x, v0.w - f1.y));
                __nv_bfloat162 l2 = __float22bfloat162_rn(make_float2(v1.x - f2.x, v1.y - f2.y));
                __nv_bfloat162 l3 = __float22bfloat162_rn(make_float2(v1.z - f3.x, v1.w - f3.y));
                *reinterpret_cast<uint4*>(aHiRow + j * 16) =
                    make_uint4(bf2u(h0), bf2u(h1), bf2u(h2), bf2u(h3));
                *reinterpret_cast<uint4*>(aLoRow + j * 16) =
                    make_uint4(bf2u(l0), bf2u(l1), bf2u(l2), bf2u(l3));
            }
        }
        __syncthreads();

        // ---- MMA mainloop ----
        float d[8][4];
        #pragma unroll
        for (int tt = 0; tt < 8; tt++) {
            d[tt][0] = 0.f; d[tt][1] = 0.f; d[tt][2] = 0.f; d[tt][3] = 0.f;
        }
        #pragma unroll
        for (int pass = 0; pass < 3; pass++) {
            uint32_t aBase = sb + (pass == 1 ? SM_ALO : SM_AHI) + aRowOff;
            uint32_t bOff  = (pass == 2 ? SM_BLO : SM_BHI) + bRowOff;
            #pragma unroll
            for (int ks = 0; ks < 8; ks++) {
                uint32_t a0, a1, a2, a3;
                LDMATRIX_X4(a0, a1, a2, a3, aBase + ks * 32);
                #pragma unroll
                for (int tt = 0; tt < 8; tt++) {
                    uint32_t b0 = *reinterpret_cast<const uint32_t*>(
                        (const char*)smem + bOff + tt * 8 * PKB + ks * 32);
                    uint32_t b1 = *reinterpret_cast<const uint32_t*>(
                        (const char*)smem + bOff + tt * 8 * PKB + ks * 32 + 16);
                    MMA_BF16(d[tt], a0, a1, a2, a3, b0, b1);
                }
            }
        }

        // ---- Epilogue ----
        float ssl = 0.f, ssh = 0.f;
        #pragma unroll
        for (int tt = 0; tt < 8; tt++) {
            int c = tt * 8 + cBase;
            float b0 = bias[c], b1 = bias[c + 1];
            d[tt][0] += b0; d[tt][1] += b1;
            d[tt][2] += b0; d[tt][3] += b1;
            ssl = fmaf(d[tt][0], d[tt][0], ssl); ssl = fmaf(d[tt][1], d[tt][1], ssl);
            ssh = fmaf(d[tt][2], d[tt][2], ssh); ssh = fmaf(d[tt][3], d[tt][3], ssh);
        }
        ssl += __shfl_xor_sync(0xffffffffu, ssl, 1);
        ssl += __shfl_xor_sync(0xffffffffu, ssl, 2);
        ssh += __shfl_xor_sync(0xffffffffu, ssh, 1);
        ssh += __shfl_xor_sync(0xffffffffu, ssh, 2);

        int rlo = r0 + warp * 16 + (lane >> 2);
        int rhi = rlo + 8;
        float invl = 1.0f / fmaxf(sqrtf(ssl), 1e-12f);
        float invh = 1.0f / fmaxf(sqrtf(ssh), 1e-12f);

        if (rlo < N) {
            float* op = out + (size_t)rlo * D + cBase;
            #pragma unroll
            for (int tt = 0; tt < 8; tt++) {
                float2 v = make_float2(d[tt][0] * invl, d[tt][1] * invl);
                if (relu) { v.x = fmaxf(v.x, 0.f); v.y = fmaxf(v.y, 0.f); }
                *reinterpret_cast<float2*>(op + tt * 8) = v;
            }
        }
        if (rhi < N) {
            float* op = out + (size_t)rhi * D + cBase;
            #pragma unroll
            for (int tt = 0; tt < 8; tt++) {
                float2 v = make_float2(d[tt][2] * invh, d[tt][3] * invh);
                if (relu) { v.x = fmaxf(v.x, 0.f); v.y = fmaxf(v.y, 0.f); }
                *reinterpret_cast<float2*>(op + tt * 8) = v;
            }
        }
        __syncthreads();   // A tile reads done before next staging
    }
}

// ---------------------------------------------------------------------------
// Launch
// ---------------------------------------------------------------------------
extern "C" void kernel_launch(void* const* d_in, const int* in_sizes, int n_in,
                              void* d_out, int out_size)
{
    const float* emb_user = (const float*)d_in[0];
    const float* emb_item = (const float*)d_in[1];
    const float* W1l_ui = (const float*)d_in[2];
    const float* b1_ui  = (const float*)d_in[3];
    const float* W1r_ui = (const float*)d_in[4];
    const float* W1l_iu = (const float*)d_in[5];
    const float* b1_iu  = (const float*)d_in[6];
    const float* W1r_iu = (const float*)d_in[7];
    const float* W2l_ui = (const float*)d_in[8];
    const float* b2_ui  = (const float*)d_in[9];
    const float* W2r_ui = (const float*)d_in[10];
    const float* W2l_iu = (const float*)d_in[11];
    const float* b2_iu  = (const float*)d_in[12];
    const float* W2r_iu = (const float*)d_in[13];
    const int* n_id_user = (const int*)d_in[14];
    const int* n_id_item = (const int*)d_in[15];
    const int* edge_ui   = (const int*)d_in[16];
    const int* edge_iu   = (const int*)d_in[17];

    const int E_ui = in_sizes[16] / 2;
    const int E_iu = in_sizes[17] / 2;

    float* out = (float*)d_out;
    float* out_user = out;
    float* out_item = out + (size_t)NU * D;

    float *acc_i, *acc_u, *h_i, *h_u;
    int *deg_i, *deg_u, *rp_i, *rp_u, *cur_i, *cur_u, *perm_ui, *perm_iu;
    int *bsum_i, *boff_i, *bsum_u, *boff_u;
    __nv_bfloat16 *Bhi, *Blo;
    cudaGetSymbolAddress((void**)&acc_i, g_acc_i);
    cudaGetSymbolAddress((void**)&acc_u, g_acc_u);
    cudaGetSymbolAddress((void**)&h_i, g_h_i);
    cudaGetSymbolAddress((void**)&h_u, g_h_u);
    cudaGetSymbolAddress((void**)&deg_i, g_deg_i);
    cudaGetSymbolAddress((void**)&deg_u, g_deg_u);
    cudaGetSymbolAddress((void**)&rp_i, g_rp_i);
    cudaGetSymbolAddress((void**)&rp_u, g_rp_u);
    cudaGetSymbolAddress((void**)&cur_i, g_cur_i);
    cudaGetSymbolAddress((void**)&cur_u, g_cur_u);
    cudaGetSymbolAddress((void**)&perm_ui, g_perm_ui);
    cudaGetSymbolAddress((void**)&perm_iu, g_perm_iu);
    cudaGetSymbolAddress((void**)&bsum_i, g_bsum_i);
    cudaGetSymbolAddress((void**)&boff_i, g_boff_i);
    cudaGetSymbolAddress((void**)&bsum_u, g_bsum_u);
    cudaGetSymbolAddress((void**)&boff_u, g_boff_u);
    cudaGetSymbolAddress((void**)&Bhi, g_Bhi);
    cudaGetSymbolAddress((void**)&Blo, g_Blo);

    const int TPB = 256;
    const int eBlocks2 = (E_ui + E_iu + TPB - 1) / TPB;
    const int aggBlocks2 = (int)(((long long)(NI + NU) * 32 + TPB - 1) / TPB);

    cudaFuncSetAttribute(sage_post_pers,
                         cudaFuncAttributeMaxDynamicSharedMemorySize, POST_SMEM);

    // ---- Prepack + CSR build ----
    prepack_w_k<<<128, 256>>>(W1l_ui, W1r_ui, W1l_iu, W1r_iu,
                              W2l_ui, W2r_ui, W2l_iu, W2r_iu);

    cudaMemsetAsync(deg_i, 0, NI * sizeof(int));
    cudaMemsetAsync(deg_u, 0, NU * sizeof(int));

    hist2_k<<<eBlocks2, TPB>>>(edge_ui + E_ui, E_ui, deg_i,
                               edge_iu + E_iu, E_iu, deg_u);
    scanA2_k<<<NB_I + NB_U, 256>>>(deg_i, NI, bsum_i, deg_u, NU, bsum_u, NB_I);
    scanB2_k<<<2, 1024>>>(bsum_i, NB_I, boff_i, rp_i, NI,
                          bsum_u, NB_U, boff_u, rp_u, NU);
    scanC2_k<<<NB_I + NB_U, 256>>>(deg_i, NI, boff_i, rp_i, cur_i,
                                   deg_u, NU, boff_u, rp_u, cur_u, NB_I);
    permute2_k<<<eBlocks2, TPB>>>(edge_ui, E_ui, cur_i, perm_ui,
                                  edge_iu, E_iu, cur_u, perm_iu);

    // ---- Layer 1 ----
    agg2_k<<<aggBlocks2, TPB>>>(emb_user, n_id_user, rp_i, perm_ui, acc_i, NI,
                                emb_item, n_id_item, rp_u, perm_iu, acc_u, NU);
    sage_post_pers<<<2 * NSM, TPB, POST_SMEM>>>(
        acc_i, emb_item, n_id_item, Bhi + 0 * 8192, Blo + 0 * 8192, b1_ui, h_i, NI,
        acc_u, emb_user, n_id_user, Bhi + 1 * 8192, Blo + 1 * 8192, b1_iu, h_u, NU,
        1);

    // ---- Layer 2 ----
    agg2_k<<<aggBlocks2, TPB>>>(h_u, nullptr, rp_i, perm_ui, acc_i, NI,
                                h_i, nullptr, rp_u, perm_iu, acc_u, NU);
    sage_post_pers<<<2 * NSM, TPB, POST_SMEM>>>(
        acc_i, h_i, nullptr, Bhi + 2 * 8192, Blo + 2 * 8192, b2_ui, out_item, NI,
        acc_u, h_u, nullptr, Bhi + 3 * 8192, Blo + 3 * 8192, b2_iu, out_user, NU,
        0);
}

// round 10
// speedup vs baseline: 1.0110x; 1.0110x over previous
#include <cuda_runtime.h>
#include <cuda_bf16.h>
#include <cstdint>

#define NU 200000
#define NI 200000
#define D  64
#define MAXE 2000000
#define NB_I ((NI + 255) / 256)
#define NB_U ((NU + 255) / 256)

// ---------------------------------------------------------------------------
// Device scratch (no cudaMalloc allowed)
// ---------------------------------------------------------------------------
__device__ float g_acc_i[(size_t)NI * D];
__device__ float g_acc_u[(size_t)NU * D];
__device__ float g_h_i[(size_t)NI * D];
__device__ float g_h_u[(size_t)NU * D];
__device__ int g_deg_i[NI];
__device__ int g_deg_u[NU];
__device__ int g_rp_i[NI + 1];
__device__ int g_rp_u[NU + 1];
__device__ int g_cur_i[NI];
__device__ int g_cur_u[NU];
__device__ int g_perm_ui[MAXE];
__device__ int g_perm_iu[MAXE];
__device__ int g_bsum[1024];
__device__ int g_boff[1024];
__device__ __nv_bfloat16 g_Bhi[4][64 * 128];
__device__ __nv_bfloat16 g_Blo[4][64 * 128];

__device__ __forceinline__ uint32_t smem_to_u32(const void* p) {
    uint32_t a;
    asm("{ .reg .u64 t; cvta.to.shared.u64 t, %1; cvt.u32.u64 %0, t; }"
        : "=r"(a) : "l"(p));
    return a;
}

// ---------------------------------------------------------------------------
// Weight prepack: B[set][n][k] = (k<64 ? Wl[k][n] : Wr[k-64][n]) split hi/lo
// ---------------------------------------------------------------------------
__global__ void prepack_w_k(const float* __restrict__ W1l_ui, const float* __restrict__ W1r_ui,
                            const float* __restrict__ W1l_iu, const float* __restrict__ W1r_iu,
                            const float* __restrict__ W2l_ui, const float* __restrict__ W2r_ui,
                            const float* __restrict__ W2l_iu, const float* __restrict__ W2r_iu)
{
    int i = blockIdx.x * blockDim.x + threadIdx.x;
    if (i >= 4 * 64 * 128) return;
    int set = i >> 13;
    int n = (i >> 7) & 63;
    int k = i & 127;
    const float* Wl; const float* Wr;
    switch (set) {
        case 0: Wl = W1l_ui; Wr = W1r_ui; break;
        case 1: Wl = W1l_iu; Wr = W1r_iu; break;
        case 2: Wl = W2l_ui; Wr = W2r_ui; break;
        default: Wl = W2l_iu; Wr = W2r_iu; break;
    }
    float w = (k < 64) ? Wl[k * D + n] : Wr[(k - 64) * D + n];
    __nv_bfloat16 hi = __float2bfloat16(w);
    __nv_bfloat16 lo = __float2bfloat16(w - __bfloat162float(hi));
    g_Bhi[set][n * 128 + k] = hi;
    g_Blo[set][n * 128 + k] = lo;
}

// ---------------------------------------------------------------------------
// CSR build
// ---------------------------------------------------------------------------
__global__ void hist_k(const int* __restrict__ dst, int E, int* __restrict__ deg)
{
    int i = blockIdx.x * blockDim.x + threadIdx.x;
    if (i < E) atomicAdd(&deg[__ldg(dst + i)], 1);
}

__global__ void scanA_k(const int* __restrict__ deg, int N, int* __restrict__ bsum)
{
    __shared__ int s[256];
    int tid = threadIdx.x;
    int i = blockIdx.x * 256 + tid;
    s[tid] = (i < N) ? deg[i] : 0;
    __syncthreads();
    #pragma unroll
    for (int o = 128; o; o >>= 1) {
        if (tid < o) s[tid] += s[tid + o];
        __syncthreads();
    }
    if (tid == 0) bsum[blockIdx.x] = s[0];
}

__global__ void scanB_k(const int* __restrict__ bsum, int NB,
                        int* __restrict__ boff, int* __restrict__ rowptr, int N)
{
    __shared__ int s[1024];
    int tid = threadIdx.x;
    int v = (tid < NB) ? bsum[tid] : 0;
    s[tid] = v;
    __syncthreads();
    for (int o = 1; o < 1024; o <<= 1) {
        int t = (tid >= o) ? s[tid - o] : 0;
        __syncthreads();
        s[tid] += t;
        __syncthreads();
    }
    if (tid < NB) boff[tid] = s[tid] - v;
    if (tid == NB - 1) rowptr[N] = s[tid];
}

__global__ void scanC_k(const int* __restrict__ deg, int N,
                        const int* __restrict__ boff,
                        int* __restrict__ rowptr, int* __restrict__ cursor)
{
    __shared__ int s[256];
    int tid = threadIdx.x;
    int i = blockIdx.x * 256 + tid;
    int v = (i < N) ? deg[i] : 0;
    s[tid] = v;
    __syncthreads();
    #pragma unroll
    for (int o = 1; o < 256; o <<= 1) {
        int t = (tid >= o) ? s[tid - o] : 0;
        __syncthreads();
        s[tid] += t;
        __syncthreads();
    }
    if (i < N) {
        int ex = boff[blockIdx.x] + s[tid] - v;
        rowptr[i] = ex;
        cursor[i] = ex;
    }
}

__global__ void permute_k(const int* __restrict__ edge, int E,
                          int* __restrict__ cursor, int* __restrict__ perm)
{
    int i = blockIdx.x * blockDim.x + threadIdx.x;
    if (i < E) {
        int s = __ldg(edge + i);
        int d = __ldg(edge + E + i);
        int slot = atomicAdd(&cursor[d], 1);
        perm[slot] = s;
    }
}

// ---------------------------------------------------------------------------
// Gather-side aggregation (mean). One warp per dst row.
// ---------------------------------------------------------------------------
__global__ void __launch_bounds__(256)
agg_k(const float* __restrict__ xsrc,
      const int*   __restrict__ remap,
      const int*   __restrict__ rowptr,
      const int*   __restrict__ perm,
      float* __restrict__ outm,
      int N)
{
    int w = (blockIdx.x * blockDim.x + threadIdx.x) >> 5;
    int lane = threadIdx.x & 31;
    if (w >= N) return;

    int start = __ldg(rowptr + w);
    int end   = __ldg(rowptr + w + 1);

    float ax = 0.0f, ay = 0.0f;
    for (int base = start; base < end; base += 32) {
        int rem = end - base;
        int idx = 0;
        if (lane < rem) {
            idx = __ldg(perm + base + lane);
            if (remap) idx = __ldg(remap + idx);
        }
        int m = rem < 32 ? rem : 32;
        for (int j = 0; j < m; j++) {
            int s2 = __shfl_sync(0xffffffffu, idx, j);
            float2 v = *reinterpret_cast<const float2*>(xsrc + (size_t)s2 * D + lane * 2);
            ax += v.x;
            ay += v.y;
        }
    }

    int deg = end - start;
    float inv = (deg > 0) ? (1.0f / (float)deg) : 0.0f;
    float2 o;
    o.x = ax * inv;
    o.y = ay * inv;
    *reinterpret_cast<float2*>(outm + (size_t)w * D + lane * 2) = o;
}

// ---------------------------------------------------------------------------
// Post GEMM on tensor cores — m32n32 warp tile, fragment-reuse mainloop.
// Warp grid: rg = warp>>1 (4 row-groups x 32 rows), cg = warp&1 (2 col-groups
// x 32 cols). Per k-step each warp loads A_hi/A_lo (2 ldmatrix.x4 each) and
// b_hi/b_lo per n-tile ONCE, issuing all 3 emulation passes from registers:
//   d += A_hi*B_hi + A_lo*B_hi + A_hi*B_lo
// Row L2-norm needs a cross-warp (col-group) smem reduction.
// ---------------------------------------------------------------------------
#define PKB 272
#define SM_AHI  0
#define SM_ALO  (128 * PKB)
#define SM_BHI  (2 * 128 * PKB)
#define SM_BLO  (SM_BHI + 64 * PKB)
#define SM_BIAS (SM_BHI + 2 * 64 * PKB)
#define SM_SS   (SM_BIAS + 256)
#define POST_SMEM (SM_SS + 1024)

#define LDMATRIX_X4(r0, r1, r2, r3, addr) \
    asm volatile("ldmatrix.sync.aligned.m8n8.x4.shared.b16 {%0, %1, %2, %3}, [%4];" \
                 : "=r"(r0), "=r"(r1), "=r"(r2), "=r"(r3) : "r"(addr))

#define MMA_BF16(d, a0, a1, a2, a3, b0, b1) \
    asm volatile("mma.sync.aligned.m16n8k16.row.col.f32.bf16.bf16.f32 " \
                 "{%0, %1, %2, %3}, {%4, %5, %6, %7}, {%8, %9}, {%0, %1, %2, %3};" \
                 : "+f"((d)[0]), "+f"((d)[1]), "+f"((d)[2]), "+f"((d)[3]) \
                 : "r"(a0), "r"(a1), "r"(a2), "r"(a3), "r"(b0), "r"(b1))

__device__ __forceinline__ uint32_t bf2u(__nv_bfloat162 v) {
    return *reinterpret_cast<uint32_t*>(&v);
}

__global__ void __launch_bounds__(256)
sage_post_tc(const float* __restrict__ acc,
             const float* __restrict__ xdst_base,
             const int*   __restrict__ remap,
             const __nv_bfloat16* __restrict__ Bhi,
             const __nv_bfloat16* __restrict__ Blo,
             const float* __restrict__ bl,
             float* __restrict__ out,
             int N, int relu)
{
    extern __shared__ char smem[];
    uint32_t sb = smem_to_u32(smem);
    const int tid = threadIdx.x;
    const int warp = tid >> 5;
    const int lane = tid & 31;
    const int r0 = blockIdx.x * 128;
    const int rg = warp >> 1;     // row group: 32 rows
    const int cg = warp & 1;      // col group: 32 cols

    // ---- Stage B from prepacked global (vectorized, conflict-free) ----
    #pragma unroll
    for (int pp = 0; pp < 4; pp++) {
        int i = tid + pp * 256;
        int n = i >> 4;
        int kq = i & 15;
        *reinterpret_cast<uint4*>(smem + SM_BHI + n * PKB + kq * 16) =
            *reinterpret_cast<const uint4*>(Bhi + n * 128 + kq * 8);
        *reinterpret_cast<uint4*>(smem + SM_BLO + n * PKB + kq * 16) =
            *reinterpret_cast<const uint4*>(Blo + n * 128 + kq * 8);
    }
    if (tid < 64) *reinterpret_cast<float*>(smem + SM_BIAS + tid * 4) = bl[tid];

    // ---- Stage A (identical to R8: row = tid&127, half = tid>>7) ----
    {
        int row  = tid & 127;
        int half = tid >> 7;
        int gr   = r0 + row;
        bool ok  = (gr < N);
        const float* p;
        if (half == 0) {
            p = acc + (size_t)(ok ? gr : 0) * D;
        } else {
            int xr = ok ? (remap ? __ldg(remap + gr) : gr) : 0;
            p = xdst_base + (size_t)xr * D;
        }
        char* aHiRow = smem + SM_AHI + row * PKB + half * 128;
        char* aLoRow = smem + SM_ALO + row * PKB + half * 128;
        #pragma unroll
        for (int j = 0; j < 8; j++) {
            float4 v0 = ok ? reinterpret_cast<const float4*>(p)[j * 2]
                           : make_float4(0.f, 0.f, 0.f, 0.f);
            float4 v1 = ok ? reinterpret_cast<const float4*>(p)[j * 2 + 1]
                           : make_float4(0.f, 0.f, 0.f, 0.f);
            __nv_bfloat162 h0 = __float22bfloat162_rn(make_float2(v0.x, v0.y));
            __nv_bfloat162 h1 = __float22bfloat162_rn(make_float2(v0.z, v0.w));
            __nv_bfloat162 h2 = __float22bfloat162_rn(make_float2(v1.x, v1.y));
            __nv_bfloat162 h3 = __float22bfloat162_rn(make_float2(v1.z, v1.w));
            float2 f0 = __bfloat1622float2(h0);
            float2 f1 = __bfloat1622float2(h1);
            float2 f2 = __bfloat1622float2(h2);
            float2 f3 = __bfloat1622float2(h3);
            __nv_bfloat162 l0 = __float22bfloat162_rn(make_float2(v0.x - f0.x, v0.y - f0.y));
            __nv_bfloat162 l1 = __float22bfloat162_rn(make_float2(v0.z - f1.x, v0.w - f1.y));
            __nv_bfloat162 l2 = __float22bfloat162_rn(make_float2(v1.x - f2.x, v1.y - f2.y));
            __nv_bfloat162 l3 = __float22bfloat162_rn(make_float2(v1.z - f3.x, v1.w - f3.y));
            *reinterpret_cast<uint4*>(aHiRow + j * 16) =
                make_uint4(bf2u(h0), bf2u(h1), bf2u(h2), bf2u(h3));
            *reinterpret_cast<uint4*>(aLoRow + j * 16) =
                make_uint4(bf2u(l0), bf2u(l1), bf2u(l2), bf2u(l3));
        }
    }
    __syncthreads();

    // ---- MMA mainloop: per ks load A_hi/A_lo + b_hi/b_lo once, 3 MMAs each ----
    float d[2][4][4];
    #pragma unroll
    for (int m = 0; m < 2; m++)
        #pragma unroll
        for (int nt = 0; nt < 4; nt++) {
            d[m][nt][0] = 0.f; d[m][nt][1] = 0.f;
            d[m][nt][2] = 0.f; d[m][nt][3] = 0.f;
        }

    const uint32_t aOff0 = (uint32_t)(rg * 32 + (lane & 15)) * PKB
                         + (uint32_t)(lane >> 4) * 16;
    const uint32_t aOff1 = aOff0 + 16 * PKB;
    const uint32_t bOffBase = (uint32_t)(cg * 32 + (lane >> 2)) * PKB
                            + (uint32_t)(lane & 3) * 4;

    #pragma unroll
    for (int ks = 0; ks < 8; ks++) {
        const uint32_t kb = ks * 32;
        uint32_t ah0[4], ah1[4], al0[4], al1[4];
        LDMATRIX_X4(ah0[0], ah0[1], ah0[2], ah0[3], sb + SM_AHI + aOff0 + kb);
        LDMATRIX_X4(ah1[0], ah1[1], ah1[2], ah1[3], sb + SM_AHI + aOff1 + kb);
        LDMATRIX_X4(al0[0], al0[1], al0[2], al0[3], sb + SM_ALO + aOff0 + kb);
        LDMATRIX_X4(al1[0], al1[1], al1[2], al1[3], sb + SM_ALO + aOff1 + kb);
        #pragma unroll
        for (int nt = 0; nt < 4; nt++) {
            uint32_t bo = bOffBase + nt * 8 * PKB + kb;
            uint32_t bh0 = *reinterpret_cast<const uint32_t*>(smem + SM_BHI + bo);
            uint32_t bh1 = *reinterpret_cast<const uint32_t*>(smem + SM_BHI + bo + 16);
            uint32_t bl0_ = *reinterpret_cast<const uint32_t*>(smem + SM_BLO + bo);
            uint32_t bl1_ = *reinterpret_cast<const uint32_t*>(smem + SM_BLO + bo + 16);
            MMA_BF16(d[0][nt], ah0[0], ah0[1], ah0[2], ah0[3], bh0, bh1);
            MMA_BF16(d[0][nt], al0[0], al0[1], al0[2], al0[3], bh0, bh1);
            MMA_BF16(d[0][nt], ah0[0], ah0[1], ah0[2], ah0[3], bl0_, bl1_);
            MMA_BF16(d[1][nt], ah1[0], ah1[1], ah1[2], ah1[3], bh0, bh1);
            MMA_BF16(d[1][nt], al1[0], al1[1], al1[2], al1[3], bh0, bh1);
            MMA_BF16(d[1][nt], ah1[0], ah1[1], ah1[2], ah1[3], bl0_, bl1_);
        }
    }

    // ---- Epilogue: bias, partial ss, cross-warp reduce, norm+relu, store ----
    const float* bias = reinterpret_cast<const float*>(smem + SM_BIAS);
    float* ssp = reinterpret_cast<float*>(smem + SM_SS);   // [128][2]
    const int cBase = (lane & 3) * 2;

    float ssLo[2], ssHi[2];
    #pragma unroll
    for (int m = 0; m < 2; m++) {
        float s0 = 0.f, s1 = 0.f;
        #pragma unroll
        for (int nt = 0; nt < 4; nt++) {
            int c = cg * 32 + nt * 8 + cBase;
            float b0 = bias[c], b1 = bias[c + 1];
            d[m][nt][0] += b0; d[m][nt][1] += b1;
            d[m][nt][2] += b0; d[m][nt][3] += b1;
            s0 = fmaf(d[m][nt][0], d[m][nt][0], s0);
            s0 = fmaf(d[m][nt][1], d[m][nt][1], s0);
            s1 = fmaf(d[m][nt][2], d[m][nt][2], s1);
            s1 = fmaf(d[m][nt][3], d[m][nt][3], s1);
        }
        s0 += __shfl_xor_sync(0xffffffffu, s0, 1);
        s0 += __shfl_xor_sync(0xffffffffu, s0, 2);
        s1 += __shfl_xor_sync(0xffffffffu, s1, 1);
        s1 += __shfl_xor_sync(0xffffffffu, s1, 2);
        ssLo[m] = s0;
        ssHi[m] = s1;
    }
    if ((lane & 3) == 0) {
        #pragma unroll
        for (int m = 0; m < 2; m++) {
            int rl = rg * 32 + m * 16 + (lane >> 2);
            ssp[rl * 2 + cg] = ssLo[m];
            ssp[(rl + 8) * 2 + cg] = ssHi[m];
        }
    }
    __syncthreads();

    #pragma unroll
    for (int m = 0; m < 2; m++) {
        int rl = rg * 32 + m * 16 + (lane >> 2);
        float fl = ssp[rl * 2] + ssp[rl * 2 + 1];
        float fh = ssp[(rl + 8) * 2] + ssp[(rl + 8) * 2 + 1];
        float invl = 1.0f / fmaxf(sqrtf(fl), 1e-12f);
        float invh = 1.0f / fmaxf(sqrtf(fh), 1e-12f);
        int glo = r0 + rl;
        int ghi = glo + 8;
        if (glo < N) {
            float* op = out + (size_t)glo * D + cg * 32 + cBase;
            #pragma unroll
            for (int nt = 0; nt < 4; nt++) {
                float2 v = make_float2(d[m][nt][0] * invl, d[m][nt][1] * invl);
                if (relu) { v.x = fmaxf(v.x, 0.f); v.y = fmaxf(v.y, 0.f); }
                *reinterpret_cast<float2*>(op + nt * 8) = v;
            }
        }
        if (ghi < N) {
            float* op = out + (size_t)ghi * D + cg * 32 + cBase;
            #pragma unroll
            for (int nt = 0; nt < 4; nt++) {
                float2 v = make_float2(d[m][nt][2] * invh, d[m][nt][3] * invh);
                if (relu) { v.x = fmaxf(v.x, 0.f); v.y = fmaxf(v.y, 0.f); }
                *reinterpret_cast<float2*>(op + nt * 8) = v;
            }
        }
    }
}

// ---------------------------------------------------------------------------
// Launch (R8 structure)
// ---------------------------------------------------------------------------
extern "C" void kernel_launch(void* const* d_in, const int* in_sizes, int n_in,
                              void* d_out, int out_size)
{
    const float* emb_user = (const float*)d_in[0];
    const float* emb_item = (const float*)d_in[1];
    const float* W1l_ui = (const float*)d_in[2];
    const float* b1_ui  = (const float*)d_in[3];
    const float* W1r_ui = (const float*)d_in[4];
    const float* W1l_iu = (const float*)d_in[5];
    const float* b1_iu  = (const float*)d_in[6];
    const float* W1r_iu = (const float*)d_in[7];
    const float* W2l_ui = (const float*)d_in[8];
    const float* b2_ui  = (const float*)d_in[9];
    const float* W2r_ui = (const float*)d_in[10];
    const float* W2l_iu = (const float*)d_in[11];
    const float* b2_iu  = (const float*)d_in[12];
    const float* W2r_iu = (const float*)d_in[13];
    const int* n_id_user = (const int*)d_in[14];
    const int* n_id_item = (const int*)d_in[15];
    const int* edge_ui   = (const int*)d_in[16];
    const int* edge_iu   = (const int*)d_in[17];

    const int E_ui = in_sizes[16] / 2;
    const int E_iu = in_sizes[17] / 2;

    float* out = (float*)d_out;
    float* out_user = out;
    float* out_item = out + (size_t)NU * D;

    float *acc_i, *acc_u, *h_i, *h_u;
    int *deg_i, *deg_u, *rp_i, *rp_u, *cur_i, *cur_u, *perm_ui, *perm_iu, *bsum, *boff;
    __nv_bfloat16 *Bhi, *Blo;
    cudaGetSymbolAddress((void**)&acc_i, g_acc_i);
    cudaGetSymbolAddress((void**)&acc_u, g_acc_u);
    cudaGetSymbolAddress((void**)&h_i, g_h_i);
    cudaGetSymbolAddress((void**)&h_u, g_h_u);
    cudaGetSymbolAddress((void**)&deg_i, g_deg_i);
    cudaGetSymbolAddress((void**)&deg_u, g_deg_u);
    cudaGetSymbolAddress((void**)&rp_i, g_rp_i);
    cudaGetSymbolAddress((void**)&rp_u, g_rp_u);
    cudaGetSymbolAddress((void**)&cur_i, g_cur_i);
    cudaGetSymbolAddress((void**)&cur_u, g_cur_u);
    cudaGetSymbolAddress((void**)&perm_ui, g_perm_ui);
    cudaGetSymbolAddress((void**)&perm_iu, g_perm_iu);
    cudaGetSymbolAddress((void**)&bsum, g_bsum);
    cudaGetSymbolAddress((void**)&boff, g_boff);
    cudaGetSymbolAddress((void**)&Bhi, g_Bhi);
    cudaGetSymbolAddress((void**)&Blo, g_Blo);

    const int TPB = 256;
    const int eBlocksUI = (E_ui + TPB - 1) / TPB;
    const int eBlocksIU = (E_iu + TPB - 1) / TPB;
    const int aggBlocksI = (NI * 32 + TPB - 1) / TPB;
    const int aggBlocksU = (NU * 32 + TPB - 1) / TPB;
    const int postBlocksI = (NI + 127) / 128;
    const int postBlocksU = (NU + 127) / 128;

    cudaFuncSetAttribute(sage_post_tc,
                         cudaFuncAttributeMaxDynamicSharedMemorySize, POST_SMEM);

    // ---- Weight prepack (once) ----
    prepack_w_k<<<128, 256>>>(W1l_ui, W1r_ui, W1l_iu, W1r_iu,
                              W2l_ui, W2r_ui, W2l_iu, W2r_iu);

    // ---- CSR build ----
    cudaMemsetAsync(deg_i, 0, NI * sizeof(int));
    cudaMemsetAsync(deg_u, 0, NU * sizeof(int));

    hist_k<<<eBlocksUI, TPB>>>(edge_ui + E_ui, E_ui, deg_i);
    hist_k<<<eBlocksIU, TPB>>>(edge_iu + E_iu, E_iu, deg_u);

    scanA_k<<<NB_I, 256>>>(deg_i, NI, bsum);
    scanB_k<<<1, 1024>>>(bsum, NB_I, boff, rp_i, NI);
    scanC_k<<<NB_I, 256>>>(deg_i, NI, boff, rp_i, cur_i);
    permute_k<<<eBlocksUI, TPB>>>(edge_ui, E_ui, cur_i, perm_ui);

    scanA_k<<<NB_U, 256>>>(deg_u, NU, bsum);
    scanB_k<<<1, 1024>>>(bsum, NB_U, boff, rp_u, NU);
    scanC_k<<<NB_U, 256>>>(deg_u, NU, boff, rp_u, cur_u);
    permute_k<<<eBlocksIU, TPB>>>(edge_iu, E_iu, cur_u, perm_iu);

    // ---- Layer 1 ----
    agg_k<<<aggBlocksI, TPB>>>(emb_user, n_id_user, rp_i, perm_ui, acc_i, NI);
    agg_k<<<aggBlocksU, TPB>>>(emb_item, n_id_item, rp_u, perm_iu, acc_u, NU);

    sage_post_tc<<<postBlocksI, TPB, POST_SMEM>>>(acc_i, emb_item, n_id_item,
                                                  Bhi + 0 * 8192, Blo + 0 * 8192,
                                                  b1_ui, h_i, NI, 1);
    sage_post_tc<<<postBlocksU, TPB, POST_SMEM>>>(acc_u, emb_user, n_id_user,
                                                  Bhi + 1 * 8192, Blo + 1 * 8192,
                                                  b1_iu, h_u, NU, 1);

    // ---- Layer 2 (same CSR) ----
    agg_k<<<aggBlocksI, TPB>>>(h_u, nullptr, rp_i, perm_ui, acc_i, NI);
    agg_k<<<aggBlocksU, TPB>>>(h_i, nullptr, rp_u, perm_iu, acc_u, NU);

    sage_post_tc<<<postBlocksI, TPB, POST_SMEM>>>(acc_i, h_i, nullptr,
                                                  Bhi + 2 * 8192, Blo + 2 * 8192,
                                                  b2_ui, out_item, NI, 0);
    sage_post_tc<<<postBlocksU, TPB, POST_SMEM>>>(acc_u, h_u, nullptr,
                                                  Bhi + 3 * 8192, Blo + 3 * 8192,
                                                  b2_iu, out_user, NU, 0);
}

// round 11
// speedup vs baseline: 1.0418x; 1.0305x over previous
#include <cuda_runtime.h>
#include <cuda_bf16.h>
#include <cstdint>

#define NU 200000
#define NI 200000
#define D  64
#define MAXE 2000000
#define NB_I ((NI + 255) / 256)
#define NB_U ((NU + 255) / 256)

// ---------------------------------------------------------------------------
// Device scratch (no cudaMalloc allowed)
// ---------------------------------------------------------------------------
__device__ float g_acc_i[(size_t)NI * D];
__device__ float g_acc_u[(size_t)NU * D];
__device__ float g_h_i[(size_t)NI * D];
__device__ float g_h_u[(size_t)NU * D];
__device__ int g_deg_i[NI];
__device__ int g_deg_u[NU];
__device__ int g_rp_i[NI + 1];
__device__ int g_rp_u[NU + 1];
__device__ int g_cur_i[NI];
__device__ int g_cur_u[NU];
__device__ int g_perm_ui[MAXE];
__device__ int g_perm_iu[MAXE];
__device__ int g_bsum_i[1024];
__device__ int g_boff_i[1024];
__device__ int g_bsum_u[1024];
__device__ int g_boff_u[1024];
__device__ __nv_bfloat16 g_Bhi[4][64 * 128];
__device__ __nv_bfloat16 g_Blo[4][64 * 128];

__device__ __forceinline__ uint32_t smem_to_u32(const void* p) {
    uint32_t a;
    asm("{ .reg .u64 t; cvta.to.shared.u64 t, %1; cvt.u32.u64 %0, t; }"
        : "=r"(a) : "l"(p));
    return a;
}

// ---------------------------------------------------------------------------
// Weight prepack
// ---------------------------------------------------------------------------
__global__ void prepack_w_k(const float* __restrict__ W1l_ui, const float* __restrict__ W1r_ui,
                            const float* __restrict__ W1l_iu, const float* __restrict__ W1r_iu,
                            const float* __restrict__ W2l_ui, const float* __restrict__ W2r_ui,
                            const float* __restrict__ W2l_iu, const float* __restrict__ W2r_iu)
{
    int i = blockIdx.x * blockDim.x + threadIdx.x;
    if (i >= 4 * 64 * 128) return;
    int set = i >> 13;
    int n = (i >> 7) & 63;
    int k = i & 127;
    const float* Wl; const float* Wr;
    switch (set) {
        case 0: Wl = W1l_ui; Wr = W1r_ui; break;
        case 1: Wl = W1l_iu; Wr = W1r_iu; break;
        case 2: Wl = W2l_ui; Wr = W2r_ui; break;
        default: Wl = W2l_iu; Wr = W2r_iu; break;
    }
    float w = (k < 64) ? Wl[k * D + n] : Wr[(k - 64) * D + n];
    __nv_bfloat16 hi = __float2bfloat16(w);
    __nv_bfloat16 lo = __float2bfloat16(w - __bfloat162float(hi));
    g_Bhi[set][n * 128 + k] = hi;
    g_Blo[set][n * 128 + k] = lo;
}

// ---------------------------------------------------------------------------
// CSR build — both sides per launch (R9 versions, verified correct)
// ---------------------------------------------------------------------------
__global__ void hist2_k(const int* __restrict__ dst0, int E0, int* __restrict__ deg0,
                        const int* __restrict__ dst1, int E1, int* __restrict__ deg1)
{
    int i = blockIdx.x * blockDim.x + threadIdx.x;
    if (i < E0) atomicAdd(&deg0[__ldg(dst0 + i)], 1);
    else if (i < E0 + E1) atomicAdd(&deg1[__ldg(dst1 + (i - E0))], 1);
}

__global__ void scanA2_k(const int* __restrict__ deg0, int N0, int* __restrict__ bsum0,
                         const int* __restrict__ deg1, int N1, int* __restrict__ bsum1,
                         int nb0)
{
    __shared__ int s[256];
    int tid = threadIdx.x;
    int side = blockIdx.x >= nb0;
    int blk = side ? blockIdx.x - nb0 : blockIdx.x;
    const int* deg = side ? deg1 : deg0;
    int N = side ? N1 : N0;
    int* bsum = side ? bsum1 : bsum0;
    int i = blk * 256 + tid;
    s[tid] = (i < N) ? deg[i] : 0;
    __syncthreads();
    #pragma unroll
    for (int o = 128; o; o >>= 1) {
        if (tid < o) s[tid] += s[tid + o];
        __syncthreads();
    }
    if (tid == 0) bsum[blk] = s[0];
}

__global__ void scanB2_k(const int* __restrict__ bsum0, int NB0, int* __restrict__ boff0,
                         int* __restrict__ rp0, int N0,
                         const int* __restrict__ bsum1, int NB1, int* __restrict__ boff1,
                         int* __restrict__ rp1, int N1)
{
    __shared__ int s[1024];
    int tid = threadIdx.x;
    const int* bsum = blockIdx.x ? bsum1 : bsum0;
    int NB = blockIdx.x ? NB1 : NB0;
    int* boff = blockIdx.x ? boff1 : boff0;
    int* rowptr = blockIdx.x ? rp1 : rp0;
    int N = blockIdx.x ? N1 : N0;
    int v = (tid < NB) ? bsum[tid] : 0;
    s[tid] = v;
    __syncthreads();
    for (int o = 1; o < 1024; o <<= 1) {
        int t = (tid >= o) ? s[tid - o] : 0;
        __syncthreads();
        s[tid] += t;
        __syncthreads();
    }
    if (tid < NB) boff[tid] = s[tid] - v;
    if (tid == NB - 1) rowptr[N] = s[tid];
}

__global__ void scanC2_k(const int* __restrict__ deg0, int N0, const int* __restrict__ boff0,
                         int* __restrict__ rp0, int* __restrict__ cur0,
                         const int* __restrict__ deg1, int N1, const int* __restrict__ boff1,
                         int* __restrict__ rp1, int* __restrict__ cur1,
                         int nb0)
{
    __shared__ int s[256];
    int tid = threadIdx.x;
    int side = blockIdx.x >= nb0;
    int blk = side ? blockIdx.x - nb0 : blockIdx.x;
    const int* deg = side ? deg1 : deg0;
    const int* boff = side ? boff1 : boff0;
    int N = side ? N1 : N0;
    int* rowptr = side ? rp1 : rp0;
    int* cursor = side ? cur1 : cur0;
    int i = blk * 256 + tid;
    int v = (i < N) ? deg[i] : 0;
    s[tid] = v;
    __syncthreads();
    #pragma unroll
    for (int o = 1; o < 256; o <<= 1) {
        int t = (tid >= o) ? s[tid - o] : 0;
        __syncthreads();
        s[tid] += t;
        __syncthreads();
    }
    if (i < N) {
        int ex = boff[blk] + s[tid] - v;
        rowptr[i] = ex;
        cursor[i] = ex;
    }
}

__global__ void permute2_k(const int* __restrict__ e0, int E0,
                           int* __restrict__ cur0, int* __restrict__ perm0,
                           const int* __restrict__ e1, int E1,
                           int* __restrict__ cur1, int* __restrict__ perm1)
{
    int i = blockIdx.x * blockDim.x + threadIdx.x;
    if (i < E0) {
        int s = __ldg(e0 + i);
        int d = __ldg(e0 + E0 + i);
        perm0[atomicAdd(&cur0[d], 1)] = s;
    } else if (i < E0 + E1) {
        int j = i - E0;
        int s = __ldg(e1 + j);
        int d = __ldg(e1 + E1 + j);
        perm1[atomicAdd(&cur1[d], 1)] = s;
    }
}

// ---------------------------------------------------------------------------
// Gather-side aggregation (mean), both sides in one launch. Warp per row.
// ---------------------------------------------------------------------------
__global__ void __launch_bounds__(256)
agg2_k(const float* __restrict__ src0, const int* __restrict__ remap0,
       const int* __restrict__ rp0, const int* __restrict__ perm0,
       float* __restrict__ out0, int N0,
       const float* __restrict__ src1, const int* __restrict__ remap1,
       const int* __restrict__ rp1, const int* __restrict__ perm1,
       float* __restrict__ out1, int N1)
{
    int w = (blockIdx.x * blockDim.x + threadIdx.x) >> 5;
    int lane = threadIdx.x & 31;
    if (w >= N0 + N1) return;

    const float* src; const int* remap; const int* rowptr; const int* perm;
    float* outm;
    if (w < N0) {
        src = src0; remap = remap0; rowptr = rp0; perm = perm0; outm = out0;
    } else {
        w -= N0;
        src = src1; remap = remap1; rowptr = rp1; perm = perm1; outm = out1;
    }

    int start = __ldg(rowptr + w);
    int end   = __ldg(rowptr + w + 1);

    float ax = 0.0f, ay = 0.0f;
    for (int base = start; base < end; base += 32) {
        int rem = end - base;
        int idx = 0;
        if (lane < rem) {
            idx = __ldg(perm + base + lane);
            if (remap) idx = __ldg(remap + idx);
        }
        int m = rem < 32 ? rem : 32;
        for (int j = 0; j < m; j++) {
            int s2 = __shfl_sync(0xffffffffu, idx, j);
            float2 v = *reinterpret_cast<const float2*>(src + (size_t)s2 * D + lane * 2);
            ax += v.x;
            ay += v.y;
        }
    }

    int deg = end - start;
    float inv = (deg > 0) ? (1.0f / (float)deg) : 0.0f;
    float2 o;
    o.x = ax * inv;
    o.y = ay * inv;
    *reinterpret_cast<float2*>(outm + (size_t)w * D + lane * 2) = o;
}

// ---------------------------------------------------------------------------
// Post GEMM on tensor cores (R8 inner code verbatim), both sides per launch.
// Blocks [0, nb0) -> side 0, [nb0, nb0+nb1) -> side 1. Non-persistent.
// ---------------------------------------------------------------------------
#define PKB 272
#define SM_AHI  0
#define SM_ALO  (128 * PKB)
#define SM_BHI  (2 * 128 * PKB)
#define SM_BLO  (SM_BHI + 64 * PKB)
#define SM_BIAS (SM_BHI + 2 * 64 * PKB)
#define POST_SMEM (SM_BIAS + 256)

#define LDMATRIX_X4(r0, r1, r2, r3, addr) \
    asm volatile("ldmatrix.sync.aligned.m8n8.x4.shared.b16 {%0, %1, %2, %3}, [%4];" \
                 : "=r"(r0), "=r"(r1), "=r"(r2), "=r"(r3) : "r"(addr))

#define MMA_BF16(d, a0, a1, a2, a3, b0, b1) \
    asm volatile("mma.sync.aligned.m16n8k16.row.col.f32.bf16.bf16.f32 " \
                 "{%0, %1, %2, %3}, {%4, %5, %6, %7}, {%8, %9}, {%0, %1, %2, %3};" \
                 : "+f"((d)[0]), "+f"((d)[1]), "+f"((d)[2]), "+f"((d)[3]) \
                 : "r"(a0), "r"(a1), "r"(a2), "r"(a3), "r"(b0), "r"(b1))

__device__ __forceinline__ uint32_t bf2u(__nv_bfloat162 v) {
    return *reinterpret_cast<uint32_t*>(&v);
}

__global__ void __launch_bounds__(256)
sage_post2_tc(const float* __restrict__ acc0, const float* __restrict__ x0,
              const int* __restrict__ remap0,
              const __nv_bfloat16* __restrict__ Bhi0, const __nv_bfloat16* __restrict__ Blo0,
              const float* __restrict__ bl0, float* __restrict__ out0, int N0, int nb0,
              const float* __restrict__ acc1, const float* __restrict__ x1,
              const int* __restrict__ remap1,
              const __nv_bfloat16* __restrict__ Bhi1, const __nv_bfloat16* __restrict__ Blo1,
              const float* __restrict__ bl1, float* __restrict__ out1, int N1,
              int relu)
{
    extern __shared__ char smem[];
    uint32_t sb = smem_to_u32(smem);
    const int tid = threadIdx.x;
    const int warp = tid >> 5;
    const int lane = tid & 31;

    const int side = blockIdx.x >= nb0;
    const float* acc = side ? acc1 : acc0;
    const float* xdst_base = side ? x1 : x0;
    const int* remap = side ? remap1 : remap0;
    const __nv_bfloat16* Bhi = side ? Bhi1 : Bhi0;
    const __nv_bfloat16* Blo = side ? Blo1 : Blo0;
    const float* bl = side ? bl1 : bl0;
    float* out = side ? out1 : out0;
    const int N = side ? N1 : N0;
    const int r0 = (side ? blockIdx.x - nb0 : blockIdx.x) * 128;

    // ---- Stage B from prepacked global ----
    #pragma unroll
    for (int pp = 0; pp < 4; pp++) {
        int i = tid + pp * 256;
        int n = i >> 4;
        int kq = i & 15;
        *reinterpret_cast<uint4*>(smem + SM_BHI + n * PKB + kq * 16) =
            *reinterpret_cast<const uint4*>(Bhi + n * 128 + kq * 8);
        *reinterpret_cast<uint4*>(smem + SM_BLO + n * PKB + kq * 16) =
            *reinterpret_cast<const uint4*>(Blo + n * 128 + kq * 8);
    }
    if (tid < 64) *reinterpret_cast<float*>(smem + SM_BIAS + tid * 4) = bl[tid];

    // ---- Stage A ----
    {
        int row  = tid & 127;
        int half = tid >> 7;
        int gr   = r0 + row;
        bool ok  = (gr < N);
        const float* p;
        if (half == 0) {
            p = acc + (size_t)(ok ? gr : 0) * D;
        } else {
            int xr = ok ? (remap ? __ldg(remap + gr) : gr) : 0;
            p = xdst_base + (size_t)xr * D;
        }
        char* aHiRow = smem + SM_AHI + row * PKB + half * 128;
        char* aLoRow = smem + SM_ALO + row * PKB + half * 128;
        #pragma unroll
        for (int j = 0; j < 8; j++) {
            float4 v0 = ok ? reinterpret_cast<const float4*>(p)[j * 2]
                           : make_float4(0.f, 0.f, 0.f, 0.f);
            float4 v1 = ok ? reinterpret_cast<const float4*>(p)[j * 2 + 1]
                           : make_float4(0.f, 0.f, 0.f, 0.f);
            __nv_bfloat162 h0 = __float22bfloat162_rn(make_float2(v0.x, v0.y));
            __nv_bfloat162 h1 = __float22bfloat162_rn(make_float2(v0.z, v0.w));
            __nv_bfloat162 h2 = __float22bfloat162_rn(make_float2(v1.x, v1.y));
            __nv_bfloat162 h3 = __float22bfloat162_rn(make_float2(v1.z, v1.w));
            float2 f0 = __bfloat1622float2(h0);
            float2 f1 = __bfloat1622float2(h1);
            float2 f2 = __bfloat1622float2(h2);
            float2 f3 = __bfloat1622float2(h3);
            __nv_bfloat162 l0 = __float22bfloat162_rn(make_float2(v0.x - f0.x, v0.y - f0.y));
            __nv_bfloat162 l1 = __float22bfloat162_rn(make_float2(v0.z - f1.x, v0.w - f1.y));
            __nv_bfloat162 l2 = __float22bfloat162_rn(make_float2(v1.x - f2.x, v1.y - f2.y));
            __nv_bfloat162 l3 = __float22bfloat162_rn(make_float2(v1.z - f3.x, v1.w - f3.y));
            *reinterpret_cast<uint4*>(aHiRow + j * 16) =
                make_uint4(bf2u(h0), bf2u(h1), bf2u(h2), bf2u(h3));
            *reinterpret_cast<uint4*>(aLoRow + j * 16) =
                make_uint4(bf2u(l0), bf2u(l1), bf2u(l2), bf2u(l3));
        }
    }
    __syncthreads();

    // ---- MMA mainloop: 3 passes x 8 k-steps, 8 n-tiles ----
    float d[8][4];
    #pragma unroll
    for (int t = 0; t < 8; t++) {
        d[t][0] = 0.f; d[t][1] = 0.f; d[t][2] = 0.f; d[t][3] = 0.f;
    }

    const uint32_t aRowOff = (uint32_t)(warp * 16 + (lane & 15)) * PKB
                           + (uint32_t)(lane >> 4) * 16;
    const uint32_t bRowOff = (uint32_t)(lane >> 2) * PKB + (uint32_t)(lane & 3) * 4;

    #pragma unroll
    for (int pass = 0; pass < 3; pass++) {
        uint32_t aBase = sb + (pass == 1 ? SM_ALO : SM_AHI) + aRowOff;
        uint32_t bOff  = (pass == 2 ? SM_BLO : SM_BHI) + bRowOff;
        #pragma unroll
        for (int ks = 0; ks < 8; ks++) {
            uint32_t a0, a1, a2, a3;
            LDMATRIX_X4(a0, a1, a2, a3, aBase + ks * 32);
            #pragma unroll
            for (int t = 0; t < 8; t++) {
                uint32_t b0 = *reinterpret_cast<const uint32_t*>(
                    (const char*)smem + bOff + t * 8 * PKB + ks * 32);
                uint32_t b1 = *reinterpret_cast<const uint32_t*>(
                    (const char*)smem + bOff + t * 8 * PKB + ks * 32 + 16);
                MMA_BF16(d[t], a0, a1, a2, a3, b0, b1);
            }
        }
    }

    // ---- Epilogue ----
    const float* bias = reinterpret_cast<const float*>(smem + SM_BIAS);
    int cBase = (lane & 3) * 2;
    float ssl = 0.f, ssh = 0.f;
    #pragma unroll
    for (int t = 0; t < 8; t++) {
        int c = t * 8 + cBase;
        float b0 = bias[c], b1 = bias[c + 1];
        d[t][0] += b0; d[t][1] += b1;
        d[t][2] += b0; d[t][3] += b1;
        ssl = fmaf(d[t][0], d[t][0], ssl); ssl = fmaf(d[t][1], d[t][1], ssl);
        ssh = fmaf(d[t][2], d[t][2], ssh); ssh = fmaf(d[t][3], d[t][3], ssh);
    }
    ssl += __shfl_xor_sync(0xffffffffu, ssl, 1);
    ssl += __shfl_xor_sync(0xffffffffu, ssl, 2);
    ssh += __shfl_xor_sync(0xffffffffu, ssh, 1);
    ssh += __shfl_xor_sync(0xffffffffu, ssh, 2);

    int rlo = r0 + warp * 16 + (lane >> 2);
    int rhi = rlo + 8;
    float invl = 1.0f / fmaxf(sqrtf(ssl), 1e-12f);
    float invh = 1.0f / fmaxf(sqrtf(ssh), 1e-12f);

    if (rlo < N) {
        float* op = out + (size_t)rlo * D + cBase;
        #pragma unroll
        for (int t = 0; t < 8; t++) {
            float2 v = make_float2(d[t][0] * invl, d[t][1] * invl);
            if (relu) { v.x = fmaxf(v.x, 0.f); v.y = fmaxf(v.y, 0.f); }
            *reinterpret_cast<float2*>(op + t * 8) = v;
        }
    }
    if (rhi < N) {
        float* op = out + (size_t)rhi * D + cBase;
        #pragma unroll
        for (int t = 0; t < 8; t++) {
            float2 v = make_float2(d[t][2] * invh, d[t][3] * invh);
            if (relu) { v.x = fmaxf(v.x, 0.f); v.y = fmaxf(v.y, 0.f); }
            *reinterpret_cast<float2*>(op + t * 8) = v;
        }
    }
}

// ---------------------------------------------------------------------------
// Launch
// ---------------------------------------------------------------------------
extern "C" void kernel_launch(void* const* d_in, const int* in_sizes, int n_in,
                              void* d_out, int out_size)
{
    const float* emb_user = (const float*)d_in[0];
    const float* emb_item = (const float*)d_in[1];
    const float* W1l_ui = (const float*)d_in[2];
    const float* b1_ui  = (const float*)d_in[3];
    const float* W1r_ui = (const float*)d_in[4];
    const float* W1l_iu = (const float*)d_in[5];
    const float* b1_iu  = (const float*)d_in[6];
    const float* W1r_iu = (const float*)d_in[7];
    const float* W2l_ui = (const float*)d_in[8];
    const float* b2_ui  = (const float*)d_in[9];
    const float* W2r_ui = (const float*)d_in[10];
    const float* W2l_iu = (const float*)d_in[11];
    const float* b2_iu  = (const float*)d_in[12];
    const float* W2r_iu = (const float*)d_in[13];
    const int* n_id_user = (const int*)d_in[14];
    const int* n_id_item = (const int*)d_in[15];
    const int* edge_ui   = (const int*)d_in[16];
    const int* edge_iu   = (const int*)d_in[17];

    const int E_ui = in_sizes[16] / 2;
    const int E_iu = in_sizes[17] / 2;

    float* out = (float*)d_out;
    float* out_user = out;
    float* out_item = out + (size_t)NU * D;

    float *acc_i, *acc_u, *h_i, *h_u;
    int *deg_i, *deg_u, *rp_i, *rp_u, *cur_i, *cur_u, *perm_ui, *perm_iu;
    int *bsum_i, *boff_i, *bsum_u, *boff_u;
    __nv_bfloat16 *Bhi, *Blo;
    cudaGetSymbolAddress((void**)&acc_i, g_acc_i);
    cudaGetSymbolAddress((void**)&acc_u, g_acc_u);
    cudaGetSymbolAddress((void**)&h_i, g_h_i);
    cudaGetSymbolAddress((void**)&h_u, g_h_u);
    cudaGetSymbolAddress((void**)&deg_i, g_deg_i);
    cudaGetSymbolAddress((void**)&deg_u, g_deg_u);
    cudaGetSymbolAddress((void**)&rp_i, g_rp_i);
    cudaGetSymbolAddress((void**)&rp_u, g_rp_u);
    cudaGetSymbolAddress((void**)&cur_i, g_cur_i);
    cudaGetSymbolAddress((void**)&cur_u, g_cur_u);
    cudaGetSymbolAddress((void**)&perm_ui, g_perm_ui);
    cudaGetSymbolAddress((void**)&perm_iu, g_perm_iu);
    cudaGetSymbolAddress((void**)&bsum_i, g_bsum_i);
    cudaGetSymbolAddress((void**)&boff_i, g_boff_i);
    cudaGetSymbolAddress((void**)&bsum_u, g_bsum_u);
    cudaGetSymbolAddress((void**)&boff_u, g_boff_u);
    cudaGetSymbolAddress((void**)&Bhi, g_Bhi);
    cudaGetSymbolAddress((void**)&Blo, g_Blo);

    const int TPB = 256;
    const int eBlocks2 = (E_ui + E_iu + TPB - 1) / TPB;
    const int aggBlocks2 = (int)(((long long)(NI + NU) * 32 + TPB - 1) / TPB);
    const int postBlocksI = (NI + 127) / 128;
    const int postBlocksU = (NU + 127) / 128;

    cudaFuncSetAttribute(sage_post2_tc,
                         cudaFuncAttributeMaxDynamicSharedMemorySize, POST_SMEM);

    // ---- Prepack + CSR build (merged) ----
    prepack_w_k<<<128, 256>>>(W1l_ui, W1r_ui, W1l_iu, W1r_iu,
                              W2l_ui, W2r_ui, W2l_iu, W2r_iu);

    cudaMemsetAsync(deg_i, 0, NI * sizeof(int));
    cudaMemsetAsync(deg_u, 0, NU * sizeof(int));

    hist2_k<<<eBlocks2, TPB>>>(edge_ui + E_ui, E_ui, deg_i,
                               edge_iu + E_iu, E_iu, deg_u);
    scanA2_k<<<NB_I + NB_U, 256>>>(deg_i, NI, bsum_i, deg_u, NU, bsum_u, NB_I);
    scanB2_k<<<2, 1024>>>(bsum_i, NB_I, boff_i, rp_i, NI,
                          bsum_u, NB_U, boff_u, rp_u, NU);
    scanC2_k<<<NB_I + NB_U, 256>>>(deg_i, NI, boff_i, rp_i, cur_i,
                                   deg_u, NU, boff_u, rp_u, cur_u, NB_I);
    permute2_k<<<eBlocks2, TPB>>>(edge_ui, E_ui, cur_i, perm_ui,
                                  edge_iu, E_iu, cur_u, perm_iu);

    // ---- Layer 1 ----
    agg2_k<<<aggBlocks2, TPB>>>(emb_user, n_id_user, rp_i, perm_ui, acc_i, NI,
                                emb_item, n_id_item, rp_u, perm_iu, acc_u, NU);
    sage_post2_tc<<<postBlocksI + postBlocksU, TPB, POST_SMEM>>>(
        acc_i, emb_item, n_id_item, Bhi + 0 * 8192, Blo + 0 * 8192, b1_ui, h_i, NI, postBlocksI,
        acc_u, emb_user, n_id_user, Bhi + 1 * 8192, Blo + 1 * 8192, b1_iu, h_u, NU,
        1);

    // ---- Layer 2 ----
    agg2_k<<<aggBlocks2, TPB>>>(h_u, nullptr, rp_i, perm_ui, acc_i, NI,
                                h_i, nullptr, rp_u, perm_iu, acc_u, NU);
    sage_post2_tc<<<postBlocksI + postBlocksU, TPB, POST_SMEM>>>(
        acc_i, h_i, nullptr, Bhi + 2 * 8192, Blo + 2 * 8192, b2_ui, out_item, NI, postBlocksI,
        acc_u, h_u, nullptr, Bhi + 3 * 8192, Blo + 3 * 8192, b2_iu, out_user, NU,
        0);
}